// round 2
// baseline (speedup 1.0000x reference)
#include <cuda_runtime.h>
#include <cuda_fp16.h>
#include <mma.h>

using namespace nvcuda;

// Problem constants (fixed by the reference).
#define N_NODES 50000
#define N_EDGES 800000
#define HDIM    128
#define NPAD    50048   // ceil(N/128)*128

// ---------------- scratch (device globals; no allocation allowed) ----------
__device__ __half g_xh   [NPAD * HDIM];      // x in fp16 (zero-padded rows)
__device__ float  g_xd   [NPAD * HDIM];      // x @ We0
__device__ float  g_xs   [NPAD * HDIM];      // x @ We1
__device__ float  g_agg  [NPAD * HDIM];      // segment_sum(m, dst)
__device__ __half g_aggh [NPAD * HDIM];
__device__ float  g_h    [NPAD * HDIM];      // agg @ Wg + bg
__device__ float  g_attn [NPAD * HDIM];      // segment_sum(h[dst], src)
__device__ __half g_attnh[NPAD * HDIM];
__device__ __half g_Weh  [3 * HDIM * HDIM];
__device__ __half g_Wgh  [HDIM * HDIM];
__device__ __half g_Woh  [HDIM * HDIM];

// ---------------- tiny utility kernels -------------------------------------
__global__ void k_zero(float* __restrict__ p, int n4) {
    int i = blockIdx.x * blockDim.x + threadIdx.x;
    if (i < n4) reinterpret_cast<float4*>(p)[i] = make_float4(0.f, 0.f, 0.f, 0.f);
}

__global__ void k_f2h(const float* __restrict__ s, __half* __restrict__ d, int n, int ntot) {
    int i = blockIdx.x * blockDim.x + threadIdx.x;
    if (i < ntot) d[i] = (i < n) ? __float2half(s[i]) : __half(0.f);
}

// ---------------- generic [M,128]@[128,128] half GEMM, fp32 out ------------
// Block: 256 threads (8 warps). Each warp computes 16 rows x 128 cols.
// Staging in shared for coalesced fp32 writes + bias add.
__global__ void k_gemm(const __half* __restrict__ A, const __half* __restrict__ B,
                       const float* __restrict__ bias, float* __restrict__ C, int nrows) {
    extern __shared__ float st[];                    // 8 * 16 * 132 floats
    const int warp = threadIdx.x >> 5;
    const int lane = threadIdx.x & 31;
    const int row0 = blockIdx.x * 128 + warp * 16;

    wmma::fragment<wmma::accumulator, 16, 16, 16, float> acc[8];
#pragma unroll
    for (int n = 0; n < 8; n++) wmma::fill_fragment(acc[n], 0.f);

#pragma unroll
    for (int k = 0; k < 8; k++) {
        wmma::fragment<wmma::matrix_a, 16, 16, 16, __half, wmma::row_major> a;
        wmma::load_matrix_sync(a, A + (size_t)row0 * 128 + k * 16, 128);
#pragma unroll
        for (int n = 0; n < 8; n++) {
            wmma::fragment<wmma::matrix_b, 16, 16, 16, __half, wmma::row_major> b;
            wmma::load_matrix_sync(b, B + (size_t)(k * 16) * 128 + n * 16, 128);
            wmma::mma_sync(acc[n], a, b, acc[n]);
        }
    }

    float* my = st + warp * 16 * 132;
#pragma unroll
    for (int n = 0; n < 8; n++)
        wmma::store_matrix_sync(my + n * 16, acc[n], 132, wmma::mem_row_major);
    __syncwarp();

    float4 bv = make_float4(0.f, 0.f, 0.f, 0.f);
    if (bias) bv = *reinterpret_cast<const float4*>(bias + lane * 4);

#pragma unroll
    for (int r = 0; r < 16; r++) {
        int gr = row0 + r;
        if (gr >= nrows) break;
        float4 v = *reinterpret_cast<const float4*>(my + r * 132 + lane * 4);
        v.x += bv.x; v.y += bv.y; v.z += bv.z; v.w += bv.w;
        *reinterpret_cast<float4*>(C + (size_t)gr * 128 + lane * 4) = v;
    }
}

// ---------------- fused edge message kernel --------------------------------
// 128 edges per block. Phase A: edge_attr tile -> half smem -> wmma vs We2.
// Phase B: m = silu(xd[dst] + xs[src] + T + be); atomicAdd into agg[dst].
__global__ void k_edge(const float* __restrict__ ea, const int* __restrict__ ei,
                       const float* __restrict__ xd, const float* __restrict__ xs,
                       const __half* __restrict__ W2, const float* __restrict__ be,
                       float* __restrict__ agg) {
    extern __shared__ char smem[];
    __half* sEA = reinterpret_cast<__half*>(smem);   // 128 x 136 halves (34816 B)
    float*  sT  = reinterpret_cast<float*>(smem);    // 128 x 132 floats (67584 B), reused

    const int tid = threadIdx.x;
    const int e0  = blockIdx.x * 128;

    // load edge_attr tile, convert to half
#pragma unroll
    for (int j = 0; j < 16; j++) {
        int idx = j * 256 + tid;           // float4 index within 128x128 tile
        int row = idx >> 5;
        int c4  = idx & 31;
        float4 v = *reinterpret_cast<const float4*>(ea + (size_t)(e0 + row) * 128 + c4 * 4);
        *reinterpret_cast<__half2*>(sEA + row * 136 + c4 * 4)     = __floats2half2_rn(v.x, v.y);
        *reinterpret_cast<__half2*>(sEA + row * 136 + c4 * 4 + 2) = __floats2half2_rn(v.z, v.w);
    }
    __syncthreads();

    const int warp = tid >> 5;
    wmma::fragment<wmma::accumulator, 16, 16, 16, float> acc[8];
#pragma unroll
    for (int n = 0; n < 8; n++) wmma::fill_fragment(acc[n], 0.f);

#pragma unroll
    for (int k = 0; k < 8; k++) {
        wmma::fragment<wmma::matrix_a, 16, 16, 16, __half, wmma::row_major> a;
        wmma::load_matrix_sync(a, sEA + warp * 16 * 136 + k * 16, 136);
#pragma unroll
        for (int n = 0; n < 8; n++) {
            wmma::fragment<wmma::matrix_b, 16, 16, 16, __half, wmma::row_major> b;
            wmma::load_matrix_sync(b, W2 + (size_t)(k * 16) * 128 + n * 16, 128);
            wmma::mma_sync(acc[n], a, b, acc[n]);
        }
    }
    __syncthreads();   // everyone done reading sEA before we overwrite with sT

    float* my = sT + warp * 16 * 132;
#pragma unroll
    for (int n = 0; n < 8; n++)
        wmma::store_matrix_sync(my + n * 16, acc[n], 132, wmma::mem_row_major);
    __syncwarp();      // each warp's phase-B threads read only its own 16 rows

    // Phase B: 2 threads per edge, 64 columns each
    const int r    = tid >> 1;
    const int hsel = tid & 1;
    const int e    = e0 + r;
    const int s = ei[e];
    const int d = ei[N_EDGES + e];

    const float* pd = xd + (size_t)d * 128;
    const float* ps = xs + (size_t)s * 128;
    const float* pt = sT + r * 132;
    float*       pa = agg + (size_t)d * 128;
    const int c0 = hsel * 64;

#pragma unroll
    for (int c = c0; c < c0 + 64; c += 4) {
        float4 a  = *reinterpret_cast<const float4*>(pd + c);
        float4 b  = *reinterpret_cast<const float4*>(ps + c);
        float4 t  = *reinterpret_cast<const float4*>(pt + c);
        float4 bb = *reinterpret_cast<const float4*>(be + c);
        float vx = a.x + b.x + t.x + bb.x;
        float vy = a.y + b.y + t.y + bb.y;
        float vz = a.z + b.z + t.z + bb.z;
        float vw = a.w + b.w + t.w + bb.w;
        vx = vx / (1.f + __expf(-vx));
        vy = vy / (1.f + __expf(-vy));
        vz = vz / (1.f + __expf(-vz));
        vw = vw / (1.f + __expf(-vw));
        atomicAdd(pa + c + 0, vx);
        atomicAdd(pa + c + 1, vy);
        atomicAdd(pa + c + 2, vz);
        atomicAdd(pa + c + 3, vw);
    }
}

// ---------------- attn scatter: attn[src] += h[dst] ------------------------
// 4 threads per edge, 32 columns each.
__global__ void k_scatter(const int* __restrict__ ei, const float* __restrict__ h,
                          float* __restrict__ attn) {
    long long idx = (long long)blockIdx.x * 256 + threadIdx.x;
    if (idx >= (long long)N_EDGES * 4) return;
    const int e = (int)(idx >> 2);
    const int q = (int)(idx & 3);
    const int s = ei[e];
    const int d = ei[N_EDGES + e];
    const float* hp = h    + (size_t)d * 128 + q * 32;
    float*       ap = attn + (size_t)s * 128 + q * 32;
#pragma unroll
    for (int c = 0; c < 32; c += 4) {
        float4 v = *reinterpret_cast<const float4*>(hp + c);
        atomicAdd(ap + c + 0, v.x);
        atomicAdd(ap + c + 1, v.y);
        atomicAdd(ap + c + 2, v.z);
        atomicAdd(ap + c + 3, v.w);
    }
}

// ---------------- launch ----------------------------------------------------
extern "C" void kernel_launch(void* const* d_in, const int* in_sizes, int n_in,
                              void* d_out, int out_size) {
    const float* x  = (const float*)d_in[0];
    const int*   ei = (const int*)d_in[1];     // int32: JAX default x64-disabled downcasts int64
    const float* ea = (const float*)d_in[2];
    const float* We = (const float*)d_in[3];
    const float* be = (const float*)d_in[4];
    const float* Wg = (const float*)d_in[5];
    const float* bg = (const float*)d_in[6];
    // d_in[7] = Wa, d_in[8] = ba : provably dead (softmax over size-1 axis == 1)
    const float* Wo = (const float*)d_in[9];
    const float* bo = (const float*)d_in[10];
    float*       out = (float*)d_out;

    void *p;
    __half *xh, *aggh, *attnh, *Weh, *Wgh, *Woh;
    float *xd, *xs, *agg, *h, *attn;
    cudaGetSymbolAddress(&p, g_xh);    xh    = (__half*)p;
    cudaGetSymbolAddress(&p, g_xd);    xd    = (float*)p;
    cudaGetSymbolAddress(&p, g_xs);    xs    = (float*)p;
    cudaGetSymbolAddress(&p, g_agg);   agg   = (float*)p;
    cudaGetSymbolAddress(&p, g_aggh);  aggh  = (__half*)p;
    cudaGetSymbolAddress(&p, g_h);     h     = (float*)p;
    cudaGetSymbolAddress(&p, g_attn);  attn  = (float*)p;
    cudaGetSymbolAddress(&p, g_attnh); attnh = (__half*)p;
    cudaGetSymbolAddress(&p, g_Weh);   Weh   = (__half*)p;
    cudaGetSymbolAddress(&p, g_Wgh);   Wgh   = (__half*)p;
    cudaGetSymbolAddress(&p, g_Woh);   Woh   = (__half*)p;

    const size_t gemm_shmem = 8 * 16 * 132 * sizeof(float);   // 67584
    const size_t edge_shmem = 128 * 132 * sizeof(float);      // 67584
    cudaFuncSetAttribute(k_gemm, cudaFuncAttributeMaxDynamicSharedMemorySize, (int)gemm_shmem);
    cudaFuncSetAttribute(k_edge, cudaFuncAttributeMaxDynamicSharedMemorySize, (int)edge_shmem);

    const int NH  = N_NODES * HDIM;      // 6,400,000
    const int NHP = NPAD * HDIM;         // 6,406,144
    const int WSZ = HDIM * HDIM;         // 16384

    // zero accumulators
    k_zero<<<(NH / 4 + 255) / 256, 256>>>(agg,  NH / 4);
    k_zero<<<(NH / 4 + 255) / 256, 256>>>(attn, NH / 4);

    // fp32 -> fp16 conversions
    k_f2h<<<(3 * WSZ + 255) / 256, 256>>>(We, Weh, 3 * WSZ, 3 * WSZ);
    k_f2h<<<(WSZ + 255) / 256, 256>>>(Wg, Wgh, WSZ, WSZ);
    k_f2h<<<(WSZ + 255) / 256, 256>>>(Wo, Woh, WSZ, WSZ);
    k_f2h<<<(NHP + 255) / 256, 256>>>(x, xh, NH, NHP);

    const int gblocks = NPAD / 128;      // 391

    // node precomputes: xd = x@We0, xs = x@We1 (be folded into edge kernel)
    k_gemm<<<gblocks, 256, gemm_shmem>>>(xh, Weh,       nullptr, xd, NPAD);
    k_gemm<<<gblocks, 256, gemm_shmem>>>(xh, Weh + WSZ, nullptr, xs, NPAD);

    // fused edge message + silu + scatter-add into agg
    k_edge<<<N_EDGES / 128, 256, edge_shmem>>>(ea, ei, xd, xs, Weh + 2 * WSZ, be, agg);

    // h = agg@Wg + bg
    k_f2h<<<(NHP + 255) / 256, 256>>>(agg, aggh, NH, NHP);
    k_gemm<<<gblocks, 256, gemm_shmem>>>(aggh, Wgh, bg, h, NPAD);

    // attn[src] += h[dst]   (alpha == 1 identically)
    k_scatter<<<(int)(((long long)N_EDGES * 4 + 255) / 256), 256>>>(ei, h, attn);

    // out = attn@Wo + bo
    k_f2h<<<(NHP + 255) / 256, 256>>>(attn, attnh, NH, NHP);
    k_gemm<<<gblocks, 256, gemm_shmem>>>(attnh, Woh, bo, out, N_NODES);
}

// round 3
// speedup vs baseline: 1.4482x; 1.4482x over previous
#include <cuda_runtime.h>
#include <cuda_fp16.h>
#include <mma.h>

using namespace nvcuda;

// Problem constants (fixed by the reference).
#define N_NODES 50000
#define N_EDGES 800000
#define HDIM    128
#define NPAD    50048   // ceil(N/128)*128

// ---------------- scratch (device globals; no allocation allowed) ----------
__device__ __half g_xh   [NPAD * HDIM];      // x in fp16 (zero-padded rows)
__device__ float  g_xd   [NPAD * HDIM];      // x @ We0
__device__ float  g_xs   [NPAD * HDIM];      // x @ We1
__device__ float  g_agg  [NPAD * HDIM];      // segment_sum(m, dst)
__device__ __half g_aggh [NPAD * HDIM];
__device__ float  g_hW   [NPAD * HDIM];      // agg @ (Wg@Wo) + bg@Wo
__device__ __half g_Weh  [3 * HDIM * HDIM];
__device__ __half g_Wch  [HDIM * HDIM];      // half(Wg@Wo)
__device__ float  g_bgwo [HDIM];             // bg@Wo

// ---------------- vector atomic helper -------------------------------------
__device__ __forceinline__ void red4(float* p, float a, float b, float c, float d) {
    asm volatile("red.global.add.v4.f32 [%0], {%1,%2,%3,%4};"
                 :: "l"(p), "f"(a), "f"(b), "f"(c), "f"(d) : "memory");
}

// ---------------- tiny utility kernels -------------------------------------
__global__ void k_zero(float* __restrict__ p, int n4) {
    int i = blockIdx.x * blockDim.x + threadIdx.x;
    if (i < n4) reinterpret_cast<float4*>(p)[i] = make_float4(0.f, 0.f, 0.f, 0.f);
}

__global__ void k_f2h(const float* __restrict__ s, __half* __restrict__ d, int n, int ntot) {
    int i = blockIdx.x * blockDim.x + threadIdx.x;
    if (i < ntot) d[i] = (i < n) ? __float2half(s[i]) : __half(0.f);
}

// out[n][:] = bo[:]  (broadcast init; also covers +bo of the final linear)
__global__ void k_binit(const float* __restrict__ bo, float* __restrict__ out) {
    int i = blockIdx.x * blockDim.x + threadIdx.x;   // float4 index
    if (i >= N_NODES * 32) return;
    reinterpret_cast<float4*>(out)[i] =
        reinterpret_cast<const float4*>(bo)[i & 31];
}

// Wc = Wg @ Wo  (fp32 accumulate, round once to half)
__global__ void k_wc(const float* __restrict__ Wg, const float* __restrict__ Wo,
                     __half* __restrict__ Wch) {
    int i = blockIdx.x * blockDim.x + threadIdx.x;   // 16384
    int r = i >> 7, c = i & 127;
    float s = 0.f;
#pragma unroll 8
    for (int k = 0; k < 128; k++) s += Wg[r * 128 + k] * Wo[k * 128 + c];
    Wch[i] = __float2half(s);
}

// bgwo = bg @ Wo
__global__ void k_bgwo(const float* __restrict__ bg, const float* __restrict__ Wo,
                       float* __restrict__ bgwo) {
    int c = threadIdx.x;                             // 128
    float s = 0.f;
#pragma unroll 8
    for (int k = 0; k < 128; k++) s += bg[k] * Wo[k * 128 + c];
    bgwo[c] = s;
}

// ---------------- generic [M,128]@[128,128] half GEMM, fp32 out ------------
__global__ void k_gemm(const __half* __restrict__ A, const __half* __restrict__ B,
                       const float* __restrict__ bias, float* __restrict__ C, int nrows) {
    extern __shared__ float st[];                    // 8 * 16 * 132 floats
    const int warp = threadIdx.x >> 5;
    const int lane = threadIdx.x & 31;
    const int row0 = blockIdx.x * 128 + warp * 16;

    wmma::fragment<wmma::accumulator, 16, 16, 16, float> acc[8];
#pragma unroll
    for (int n = 0; n < 8; n++) wmma::fill_fragment(acc[n], 0.f);

#pragma unroll
    for (int k = 0; k < 8; k++) {
        wmma::fragment<wmma::matrix_a, 16, 16, 16, __half, wmma::row_major> a;
        wmma::load_matrix_sync(a, A + (size_t)row0 * 128 + k * 16, 128);
#pragma unroll
        for (int n = 0; n < 8; n++) {
            wmma::fragment<wmma::matrix_b, 16, 16, 16, __half, wmma::row_major> b;
            wmma::load_matrix_sync(b, B + (size_t)(k * 16) * 128 + n * 16, 128);
            wmma::mma_sync(acc[n], a, b, acc[n]);
        }
    }

    float* my = st + warp * 16 * 132;
#pragma unroll
    for (int n = 0; n < 8; n++)
        wmma::store_matrix_sync(my + n * 16, acc[n], 132, wmma::mem_row_major);
    __syncwarp();

    float4 bv = make_float4(0.f, 0.f, 0.f, 0.f);
    if (bias) bv = *reinterpret_cast<const float4*>(bias + lane * 4);

#pragma unroll
    for (int r = 0; r < 16; r++) {
        int gr = row0 + r;
        if (gr >= nrows) break;
        float4 v = *reinterpret_cast<const float4*>(my + r * 132 + lane * 4);
        v.x += bv.x; v.y += bv.y; v.z += bv.z; v.w += bv.w;
        *reinterpret_cast<float4*>(C + (size_t)gr * 128 + lane * 4) = v;
    }
}

// ---------------- fused edge message kernel --------------------------------
// 128 edges/block. Phase A: edge_attr tile -> half smem -> wmma vs We2.
// Phase B: m = silu(xd[dst] + xs[src] + T + be); red.v4 into agg[dst].
__global__ void k_edge(const float* __restrict__ ea, const int* __restrict__ ei,
                       const float* __restrict__ xd, const float* __restrict__ xs,
                       const __half* __restrict__ W2, const float* __restrict__ be,
                       float* __restrict__ agg) {
    extern __shared__ char smem[];
    __half* sEA = reinterpret_cast<__half*>(smem);   // 128 x 136 halves
    float*  sT  = reinterpret_cast<float*>(smem);    // 128 x 132 floats, reused

    const int tid = threadIdx.x;
    const int e0  = blockIdx.x * 128;

#pragma unroll
    for (int j = 0; j < 16; j++) {
        int idx = j * 256 + tid;           // float4 index within 128x128 tile
        int row = idx >> 5;
        int c4  = idx & 31;
        float4 v = *reinterpret_cast<const float4*>(ea + (size_t)(e0 + row) * 128 + c4 * 4);
        *reinterpret_cast<__half2*>(sEA + row * 136 + c4 * 4)     = __floats2half2_rn(v.x, v.y);
        *reinterpret_cast<__half2*>(sEA + row * 136 + c4 * 4 + 2) = __floats2half2_rn(v.z, v.w);
    }
    __syncthreads();

    const int warp = tid >> 5;
    wmma::fragment<wmma::accumulator, 16, 16, 16, float> acc[8];
#pragma unroll
    for (int n = 0; n < 8; n++) wmma::fill_fragment(acc[n], 0.f);

#pragma unroll
    for (int k = 0; k < 8; k++) {
        wmma::fragment<wmma::matrix_a, 16, 16, 16, __half, wmma::row_major> a;
        wmma::load_matrix_sync(a, sEA + warp * 16 * 136 + k * 16, 136);
#pragma unroll
        for (int n = 0; n < 8; n++) {
            wmma::fragment<wmma::matrix_b, 16, 16, 16, __half, wmma::row_major> b;
            wmma::load_matrix_sync(b, W2 + (size_t)(k * 16) * 128 + n * 16, 128);
            wmma::mma_sync(acc[n], a, b, acc[n]);
        }
    }
    __syncthreads();   // done reading sEA before overwrite with sT

    float* my = sT + warp * 16 * 132;
#pragma unroll
    for (int n = 0; n < 8; n++)
        wmma::store_matrix_sync(my + n * 16, acc[n], 132, wmma::mem_row_major);
    __syncwarp();      // phase-B threads of this warp read only its own rows

    // Phase B: 2 threads per edge, 64 columns each
    const int r    = tid >> 1;
    const int hsel = tid & 1;
    const int e    = e0 + r;
    const int s = ei[e];
    const int d = ei[N_EDGES + e];

    const float* pd = xd + (size_t)d * 128;
    const float* ps = xs + (size_t)s * 128;
    const float* pt = sT + r * 132;
    float*       pa = agg + (size_t)d * 128;
    const int c0 = hsel * 64;

#pragma unroll
    for (int c = c0; c < c0 + 64; c += 4) {
        float4 a  = *reinterpret_cast<const float4*>(pd + c);
        float4 b  = *reinterpret_cast<const float4*>(ps + c);
        float4 t  = *reinterpret_cast<const float4*>(pt + c);
        float4 bb = *reinterpret_cast<const float4*>(be + c);
        float vx = a.x + b.x + t.x + bb.x;
        float vy = a.y + b.y + t.y + bb.y;
        float vz = a.z + b.z + t.z + bb.z;
        float vw = a.w + b.w + t.w + bb.w;
        vx = vx / (1.f + __expf(-vx));
        vy = vy / (1.f + __expf(-vy));
        vz = vz / (1.f + __expf(-vz));
        vw = vw / (1.f + __expf(-vw));
        red4(pa + c, vx, vy, vz, vw);
    }
}

// ---------------- final scatter: out[src] += hW[dst] ------------------------
// 2 threads per edge, 64 columns each, red.v4.
__global__ void k_scatter(const int* __restrict__ ei, const float* __restrict__ hw,
                          float* __restrict__ out) {
    int idx = blockIdx.x * 256 + threadIdx.x;
    if (idx >= N_EDGES * 2) return;
    const int e    = idx >> 1;
    const int hsel = idx & 1;
    const int s = ei[e];
    const int d = ei[N_EDGES + e];
    const float* hp = hw  + (size_t)d * 128 + hsel * 64;
    float*       op = out + (size_t)s * 128 + hsel * 64;
#pragma unroll
    for (int c = 0; c < 64; c += 4) {
        float4 v = *reinterpret_cast<const float4*>(hp + c);
        red4(op + c, v.x, v.y, v.z, v.w);
    }
}

// ---------------- launch ----------------------------------------------------
extern "C" void kernel_launch(void* const* d_in, const int* in_sizes, int n_in,
                              void* d_out, int out_size) {
    const float* x  = (const float*)d_in[0];
    const int*   ei = (const int*)d_in[1];     // int32 (JAX x64 disabled)
    const float* ea = (const float*)d_in[2];
    const float* We = (const float*)d_in[3];
    const float* be = (const float*)d_in[4];
    const float* Wg = (const float*)d_in[5];
    const float* bg = (const float*)d_in[6];
    // d_in[7]=Wa, d_in[8]=ba: dead (softmax over size-1 axis == 1)
    const float* Wo = (const float*)d_in[9];
    const float* bo = (const float*)d_in[10];
    float*       out = (float*)d_out;

    void *p;
    __half *xh, *aggh, *Weh, *Wch;
    float *xd, *xs, *agg, *hW, *bgwo;
    cudaGetSymbolAddress(&p, g_xh);   xh   = (__half*)p;
    cudaGetSymbolAddress(&p, g_xd);   xd   = (float*)p;
    cudaGetSymbolAddress(&p, g_xs);   xs   = (float*)p;
    cudaGetSymbolAddress(&p, g_agg);  agg  = (float*)p;
    cudaGetSymbolAddress(&p, g_aggh); aggh = (__half*)p;
    cudaGetSymbolAddress(&p, g_hW);   hW   = (float*)p;
    cudaGetSymbolAddress(&p, g_Weh);  Weh  = (__half*)p;
    cudaGetSymbolAddress(&p, g_Wch);  Wch  = (__half*)p;
    cudaGetSymbolAddress(&p, g_bgwo); bgwo = (float*)p;

    const size_t gemm_shmem = 8 * 16 * 132 * sizeof(float);   // 67584
    const size_t edge_shmem = 128 * 132 * sizeof(float);      // 67584
    cudaFuncSetAttribute(k_gemm, cudaFuncAttributeMaxDynamicSharedMemorySize, (int)gemm_shmem);
    cudaFuncSetAttribute(k_edge, cudaFuncAttributeMaxDynamicSharedMemorySize, (int)edge_shmem);

    const int NH  = N_NODES * HDIM;      // 6,400,000
    const int NHP = NPAD * HDIM;         // 6,406,144
    const int WSZ = HDIM * HDIM;         // 16384
    const int gblocks = NPAD / 128;      // 391

    // Launches 1-5 (ncu -s 5 skips these; #6 = k_edge gets profiled)
    k_f2h<<<(3 * WSZ + 255) / 256, 256>>>(We, Weh, 3 * WSZ, 3 * WSZ);     // 1
    k_f2h<<<(NHP + 255) / 256, 256>>>(x, xh, NH, NHP);                    // 2
    k_gemm<<<gblocks, 256, gemm_shmem>>>(xh, Weh,       nullptr, xd, NPAD); // 3
    k_gemm<<<gblocks, 256, gemm_shmem>>>(xh, Weh + WSZ, nullptr, xs, NPAD); // 4
    k_zero<<<(NH / 4 + 255) / 256, 256>>>(agg, NH / 4);                   // 5

    // 6: fused edge message + silu + vector-atomic scatter into agg
    k_edge<<<N_EDGES / 128, 256, edge_shmem>>>(ea, ei, xd, xs, Weh + 2 * WSZ, be, agg);

    // fold Wg and Wo: Wc = Wg@Wo, bgwo = bg@Wo
    k_wc<<<64, 256>>>(Wg, Wo, Wch);
    k_bgwo<<<1, 128>>>(bg, Wo, bgwo);
    k_binit<<<(N_NODES * 32 + 255) / 256, 256>>>(bo, out);

    // hW = agg @ Wc + bgwo
    k_f2h<<<(NHP + 255) / 256, 256>>>(agg, aggh, NH, NHP);
    k_gemm<<<gblocks, 256, gemm_shmem>>>(aggh, Wch, bgwo, hW, NPAD);

    // out[src] += hW[dst]
    k_scatter<<<(N_EDGES * 2 + 255) / 256, 256>>>(ei, hW, out);
}

// round 4
// speedup vs baseline: 2.6997x; 1.8642x over previous
#include <cuda_runtime.h>
#include <cuda_fp16.h>
#include <mma.h>

using namespace nvcuda;

#define N_NODES 50000
#define N_EDGES 800000
#define HDIM    128
#define NPAD    50048           // ceil(N/128)*128
#define WSZ     (HDIM * HDIM)

// ---------------- scratch (device globals; no allocation allowed) ----------
__device__ __half g_xh   [NPAD * HDIM];
__device__ float  g_xd   [NPAD * HDIM];              // x @ We0
__device__ float  g_xs   [NPAD * HDIM];              // x @ We1
__device__ float  g_agg  [NPAD * HDIM];
__device__ __half g_aggh [NPAD * HDIM];
__device__ float  g_hW   [NPAD * HDIM];              // agg @ (Wg@Wo) + bg@Wo
__device__ __half g_eawh [(size_t)N_EDGES * HDIM];   // half(ea @ We2), 205MB
__device__ __half g_Weh  [3 * WSZ];
__device__ __half g_Wch  [WSZ];                      // half(Wg@Wo)
__device__ float  g_bgwo [HDIM];                     // bg@Wo
// CSR machinery
__device__ int g_deg_in [N_NODES];
__device__ int g_deg_out[N_NODES];
__device__ int g_off_in [N_NODES + 1];
__device__ int g_off_out[N_NODES + 1];
__device__ int g_cur_in [N_NODES];
__device__ int g_cur_out[N_NODES];
__device__ int g_csr_in_src[N_EDGES];   // in-CSR: source node per in-edge
__device__ int g_csr_in_eid[N_EDGES];   // in-CSR: original edge id (for eaW)
__device__ int g_csr_out_dst[N_EDGES];  // out-CSR: dest node per out-edge

// ---------------- small utility kernels ------------------------------------
__global__ void k_f2h(const float* __restrict__ s, __half* __restrict__ d, int n, int ntot) {
    int i = blockIdx.x * blockDim.x + threadIdx.x;
    if (i < ntot) d[i] = (i < n) ? __float2half(s[i]) : __half(0.f);
}

__global__ void k_hist(const int* __restrict__ ei, int* __restrict__ din, int* __restrict__ dout) {
    int e = blockIdx.x * 256 + threadIdx.x;
    if (e >= N_EDGES) return;
    atomicAdd(&dout[ei[e]], 1);            // src
    atomicAdd(&din[ei[N_EDGES + e]], 1);   // dst
}

// single-block exclusive scan of a 50K int array (+ cursor copy)
__global__ void k_scan(const int* __restrict__ deg, int* __restrict__ off, int* __restrict__ cur) {
    __shared__ int sp[1024];
    const int t = threadIdx.x;
    const int CH = 49;                               // 1024*49 >= 50000
    int start = t * CH;
    int end   = start + CH; if (end > N_NODES) end = N_NODES;
    int sum = 0;
    for (int i = start; i < end; i++) sum += deg[i];
    sp[t] = sum;
    __syncthreads();
    for (int d = 1; d < 1024; d <<= 1) {
        int v = (t >= d) ? sp[t - d] : 0;
        __syncthreads();
        sp[t] += v;
        __syncthreads();
    }
    int run = (t == 0) ? 0 : sp[t - 1];
    for (int i = start; i < end; i++) { off[i] = run; cur[i] = run; run += deg[i]; }
    if (start < N_NODES && end == N_NODES) off[N_NODES] = run;
}

__global__ void k_scatteridx(const int* __restrict__ ei,
                             int* __restrict__ cin, int* __restrict__ cout,
                             int* __restrict__ isrc, int* __restrict__ ieid,
                             int* __restrict__ odst) {
    int e = blockIdx.x * 256 + threadIdx.x;
    if (e >= N_EDGES) return;
    int s = ei[e];
    int d = ei[N_EDGES + e];
    int p1 = atomicAdd(&cin[d], 1);
    isrc[p1] = s; ieid[p1] = e;
    int p2 = atomicAdd(&cout[s], 1);
    odst[p2] = d;
}

// Wc = Wg @ Wo  (fp32 accumulate, round once to half)
__global__ void k_wc(const float* __restrict__ Wg, const float* __restrict__ Wo,
                     __half* __restrict__ Wch) {
    int i = blockIdx.x * blockDim.x + threadIdx.x;
    int r = i >> 7, c = i & 127;
    float s = 0.f;
#pragma unroll 8
    for (int k = 0; k < 128; k++) s += Wg[r * 128 + k] * Wo[k * 128 + c];
    Wch[i] = __float2half(s);
}

__global__ void k_bgwo(const float* __restrict__ bg, const float* __restrict__ Wo,
                       float* __restrict__ bgwo) {
    int c = threadIdx.x;
    float s = 0.f;
#pragma unroll 8
    for (int k = 0; k < 128; k++) s += bg[k] * Wo[k * 128 + c];
    bgwo[c] = s;
}

// ---------------- [128rows,128]@[128,128] GEMM, B staged in shared ---------
// grid covers NPAD/128 blocks; all written rows exist (padded buffers).
__global__ void k_gemm(const __half* __restrict__ A, const __half* __restrict__ B,
                       const float* __restrict__ bias, float* __restrict__ C) {
    extern __shared__ char smem[];
    __half* sB = reinterpret_cast<__half*>(smem);    // 128 x 136 halves
    float*  sT = reinterpret_cast<float*>(smem);     // reused for staging out

    const int tid  = threadIdx.x;
    const int warp = tid >> 5;
    const int lane = tid & 31;

#pragma unroll
    for (int j = 0; j < 32; j++) {                   // 8192 half2
        int idx = j * 256 + tid;
        int row = idx >> 6, c2 = idx & 63;
        *reinterpret_cast<__half2*>(sB + row * 136 + c2 * 2) =
            *reinterpret_cast<const __half2*>(B + row * 128 + c2 * 2);
    }
    __syncthreads();

    const int row0 = blockIdx.x * 128 + warp * 16;
    wmma::fragment<wmma::accumulator, 16, 16, 16, float> acc[8];
#pragma unroll
    for (int n = 0; n < 8; n++) wmma::fill_fragment(acc[n], 0.f);

#pragma unroll
    for (int k = 0; k < 8; k++) {
        wmma::fragment<wmma::matrix_a, 16, 16, 16, __half, wmma::row_major> a;
        wmma::load_matrix_sync(a, A + (size_t)row0 * 128 + k * 16, 128);
#pragma unroll
        for (int n = 0; n < 8; n++) {
            wmma::fragment<wmma::matrix_b, 16, 16, 16, __half, wmma::row_major> b;
            wmma::load_matrix_sync(b, sB + (k * 16) * 136 + n * 16, 136);
            wmma::mma_sync(acc[n], a, b, acc[n]);
        }
    }
    __syncthreads();                                 // done with sB

    float* my = sT + warp * 16 * 132;
#pragma unroll
    for (int n = 0; n < 8; n++)
        wmma::store_matrix_sync(my + n * 16, acc[n], 132, wmma::mem_row_major);
    __syncwarp();

    float4 bv = make_float4(0.f, 0.f, 0.f, 0.f);
    if (bias) bv = *reinterpret_cast<const float4*>(bias + lane * 4);

#pragma unroll
    for (int r = 0; r < 16; r++) {
        float4 v = *reinterpret_cast<const float4*>(my + r * 132 + lane * 4);
        v.x += bv.x; v.y += bv.y; v.z += bv.z; v.w += bv.w;
        *reinterpret_cast<float4*>(C + (size_t)(row0 + r) * 128 + lane * 4) = v;
    }
}

// ---------------- eaW = half(ea @ We2): fp32 in, half out ------------------
__global__ void k_eaw(const float* __restrict__ ea, const __half* __restrict__ W2,
                      __half* __restrict__ eaw) {
    extern __shared__ char smem[];
    __half* sA = reinterpret_cast<__half*>(smem);            // 128 x 136
    __half* sB = reinterpret_cast<__half*>(smem + 34816);    // 128 x 136
    float*  sT = reinterpret_cast<float*>(smem);             // reused

    const int tid  = threadIdx.x;
    const int warp = tid >> 5;
    const size_t e0 = (size_t)blockIdx.x * 128;

#pragma unroll
    for (int j = 0; j < 16; j++) {                   // 4096 float4 of A tile
        int idx = j * 256 + tid;
        int row = idx >> 5, c4 = idx & 31;
        float4 v = *reinterpret_cast<const float4*>(ea + (e0 + row) * 128 + c4 * 4);
        *reinterpret_cast<__half2*>(sA + row * 136 + c4 * 4)     = __floats2half2_rn(v.x, v.y);
        *reinterpret_cast<__half2*>(sA + row * 136 + c4 * 4 + 2) = __floats2half2_rn(v.z, v.w);
    }
#pragma unroll
    for (int j = 0; j < 32; j++) {                   // stage W2
        int idx = j * 256 + tid;
        int row = idx >> 6, c2 = idx & 63;
        *reinterpret_cast<__half2*>(sB + row * 136 + c2 * 2) =
            *reinterpret_cast<const __half2*>(W2 + row * 128 + c2 * 2);
    }
    __syncthreads();

    wmma::fragment<wmma::accumulator, 16, 16, 16, float> acc[8];
#pragma unroll
    for (int n = 0; n < 8; n++) wmma::fill_fragment(acc[n], 0.f);

#pragma unroll
    for (int k = 0; k < 8; k++) {
        wmma::fragment<wmma::matrix_a, 16, 16, 16, __half, wmma::row_major> a;
        wmma::load_matrix_sync(a, sA + warp * 16 * 136 + k * 16, 136);
#pragma unroll
        for (int n = 0; n < 8; n++) {
            wmma::fragment<wmma::matrix_b, 16, 16, 16, __half, wmma::row_major> b;
            wmma::load_matrix_sync(b, sB + (k * 16) * 136 + n * 16, 136);
            wmma::mma_sync(acc[n], a, b, acc[n]);
        }
    }
    __syncthreads();                                 // done reading sA/sB

    float* my = sT + warp * 16 * 132;
#pragma unroll
    for (int n = 0; n < 8; n++)
        wmma::store_matrix_sync(my + n * 16, acc[n], 132, wmma::mem_row_major);
    __syncthreads();                                 // write loop spans all warps' rows

#pragma unroll
    for (int j = 0; j < 32; j++) {                   // 8192 half2 out
        int idx = j * 256 + tid;
        int row = idx >> 6, c2 = idx & 63;
        float x0 = sT[row * 132 + c2 * 2];
        float x1 = sT[row * 132 + c2 * 2 + 1];
        *reinterpret_cast<__half2*>(eaw + (e0 + row) * 128 + c2 * 2) = __floats2half2_rn(x0, x1);
    }
}

// ---------------- aggregation: agg[n] = sum_in silu(xd[n]+be + xs[s] + eaW[e])
__device__ __forceinline__ float silu1(float v) { return v / (1.f + __expf(-v)); }

__global__ void k_agg(const int* __restrict__ off, const int* __restrict__ csrs,
                      const int* __restrict__ csre,
                      const float* __restrict__ xd, const float* __restrict__ xs,
                      const __half* __restrict__ eaw, const float* __restrict__ be,
                      float* __restrict__ agg) {
    const int w    = (blockIdx.x * 256 + threadIdx.x) >> 5;    // node id
    const int lane = threadIdx.x & 31;
    if (w >= N_NODES) return;

    float4 base = *reinterpret_cast<const float4*>(xd + (size_t)w * 128 + lane * 4);
    float4 bb   = *reinterpret_cast<const float4*>(be + lane * 4);
    base.x += bb.x; base.y += bb.y; base.z += bb.z; base.w += bb.w;

    float4 acc = make_float4(0.f, 0.f, 0.f, 0.f);
    const int beg = off[w], end = off[w + 1];
    for (int i = beg; i < end; i++) {
        int s = csrs[i];
        int e = csre[i];
        float4 v = *reinterpret_cast<const float4*>(xs + (size_t)s * 128 + lane * 4);
        const __half2* ph = reinterpret_cast<const __half2*>(eaw + (size_t)e * 128 + lane * 4);
        float2 p0 = __half22float2(ph[0]);
        float2 p1 = __half22float2(ph[1]);
        acc.x += silu1(base.x + v.x + p0.x);
        acc.y += silu1(base.y + v.y + p0.y);
        acc.z += silu1(base.z + v.z + p1.x);
        acc.w += silu1(base.w + v.w + p1.y);
    }
    *reinterpret_cast<float4*>(agg + (size_t)w * 128 + lane * 4) = acc;
}

// ---------------- output: out[n] = bo + sum_out hW[dst] ---------------------
__global__ void k_out(const int* __restrict__ off, const int* __restrict__ odst,
                      const float* __restrict__ hW, const float* __restrict__ bo,
                      float* __restrict__ out) {
    const int w    = (blockIdx.x * 256 + threadIdx.x) >> 5;
    const int lane = threadIdx.x & 31;
    if (w >= N_NODES) return;

    float4 acc = *reinterpret_cast<const float4*>(bo + lane * 4);
    const int beg = off[w], end = off[w + 1];
    for (int i = beg; i < end; i++) {
        int d = odst[i];
        float4 v = *reinterpret_cast<const float4*>(hW + (size_t)d * 128 + lane * 4);
        acc.x += v.x; acc.y += v.y; acc.z += v.z; acc.w += v.w;
    }
    *reinterpret_cast<float4*>(out + (size_t)w * 128 + lane * 4) = acc;
}

// ---------------- launch ----------------------------------------------------
extern "C" void kernel_launch(void* const* d_in, const int* in_sizes, int n_in,
                              void* d_out, int out_size) {
    const float* x  = (const float*)d_in[0];
    const int*   ei = (const int*)d_in[1];     // int32 (JAX x64 disabled)
    const float* ea = (const float*)d_in[2];
    const float* We = (const float*)d_in[3];
    const float* be = (const float*)d_in[4];
    const float* Wg = (const float*)d_in[5];
    const float* bg = (const float*)d_in[6];
    // d_in[7]=Wa, d_in[8]=ba: dead (softmax over size-1 axis == 1)
    const float* Wo = (const float*)d_in[9];
    const float* bo = (const float*)d_in[10];
    float*       out = (float*)d_out;

    void *p;
    __half *xh, *aggh, *eawh, *Weh, *Wch;
    float *xd, *xs, *agg, *hW, *bgwo;
    int *din, *dout_, *oin, *oout, *cin, *cout_, *isrc, *ieid, *odst;
    cudaGetSymbolAddress(&p, g_xh);          xh    = (__half*)p;
    cudaGetSymbolAddress(&p, g_xd);          xd    = (float*)p;
    cudaGetSymbolAddress(&p, g_xs);          xs    = (float*)p;
    cudaGetSymbolAddress(&p, g_agg);         agg   = (float*)p;
    cudaGetSymbolAddress(&p, g_aggh);        aggh  = (__half*)p;
    cudaGetSymbolAddress(&p, g_hW);          hW    = (float*)p;
    cudaGetSymbolAddress(&p, g_eawh);        eawh  = (__half*)p;
    cudaGetSymbolAddress(&p, g_Weh);         Weh   = (__half*)p;
    cudaGetSymbolAddress(&p, g_Wch);         Wch   = (__half*)p;
    cudaGetSymbolAddress(&p, g_bgwo);        bgwo  = (float*)p;
    cudaGetSymbolAddress(&p, g_deg_in);      din   = (int*)p;
    cudaGetSymbolAddress(&p, g_deg_out);     dout_ = (int*)p;
    cudaGetSymbolAddress(&p, g_off_in);      oin   = (int*)p;
    cudaGetSymbolAddress(&p, g_off_out);     oout  = (int*)p;
    cudaGetSymbolAddress(&p, g_cur_in);      cin   = (int*)p;
    cudaGetSymbolAddress(&p, g_cur_out);     cout_ = (int*)p;
    cudaGetSymbolAddress(&p, g_csr_in_src);  isrc  = (int*)p;
    cudaGetSymbolAddress(&p, g_csr_in_eid);  ieid  = (int*)p;
    cudaGetSymbolAddress(&p, g_csr_out_dst); odst  = (int*)p;

    const size_t gemm_shmem = 67584;
    const size_t eaw_shmem  = 69632;
    cudaFuncSetAttribute(k_gemm, cudaFuncAttributeMaxDynamicSharedMemorySize, (int)gemm_shmem);
    cudaFuncSetAttribute(k_eaw,  cudaFuncAttributeMaxDynamicSharedMemorySize, (int)eaw_shmem);

    const int NH  = N_NODES * HDIM;
    const int NHP = NPAD * HDIM;
    const int gblocks = NPAD / 128;           // 391
    const int eblocks = N_EDGES / 128;        // 6250
    const int nwarp_blocks = (N_NODES * 32 + 255) / 256;   // 6250

    // ---- CSR construction ----
    cudaMemsetAsync(din,   0, N_NODES * sizeof(int));
    cudaMemsetAsync(dout_, 0, N_NODES * sizeof(int));
    k_hist<<<(N_EDGES + 255) / 256, 256>>>(ei, din, dout_);
    k_scan<<<1, 1024>>>(din,   oin,  cin);
    k_scan<<<1, 1024>>>(dout_, oout, cout_);
    k_scatteridx<<<(N_EDGES + 255) / 256, 256>>>(ei, cin, cout_, isrc, ieid, odst);

    // ---- weight/feature prep ----
    k_f2h<<<(3 * WSZ + 255) / 256, 256>>>(We, Weh, 3 * WSZ, 3 * WSZ);
    k_f2h<<<(NHP + 255) / 256, 256>>>(x, xh, NH, NHP);
    k_wc<<<64, 256>>>(Wg, Wo, Wch);
    k_bgwo<<<1, 128>>>(bg, Wo, bgwo);

    // ---- node precomputes ----
    k_gemm<<<gblocks, 256, gemm_shmem>>>(xh, Weh,       nullptr, xd);
    k_gemm<<<gblocks, 256, gemm_shmem>>>(xh, Weh + WSZ, nullptr, xs);

    // ---- edge GEMM: eaW = half(ea @ We2) ----
    k_eaw<<<eblocks, 256, eaw_shmem>>>(ea, Weh + 2 * WSZ, eawh);

    // ---- atomic-free aggregation ----
    k_agg<<<nwarp_blocks, 256>>>(oin, isrc, ieid, xd, xs, eawh, be, agg);

    // ---- hW = agg @ (Wg@Wo) + bg@Wo ----
    k_f2h<<<(NHP + 255) / 256, 256>>>(agg, aggh, NH, NHP);
    k_gemm<<<gblocks, 256, gemm_shmem>>>(aggh, Wch, bgwo, hW);

    // ---- atomic-free output scatter ----
    k_out<<<nwarp_blocks, 256>>>(oout, odst, hW, bo, out);
}